// round 16
// baseline (speedup 1.0000x reference)
#include <cuda_runtime.h>
#include <cstdint>

#define NPAP 4096
#define NAUT 2048
#define HD   128
#define CANDMAX 1024
#define SMEMB 27136

// ---------------- threefry2x32 (JAX, 20 rounds) ----------------
__host__ __device__ __forceinline__ void tf2x32(unsigned k0, unsigned k1,
                                                unsigned x0, unsigned x1,
                                                unsigned &o0, unsigned &o1) {
  unsigned ks2 = k0 ^ k1 ^ 0x1BD11BDAu;
  x0 += k0; x1 += k1;
#define TFR(r) { x0 += x1; x1 = (x1 << (r)) | (x1 >> (32 - (r))); x1 ^= x0; }
  TFR(13) TFR(15) TFR(26) TFR(6)  x0 += k1;  x1 += ks2 + 1u;
  TFR(17) TFR(29) TFR(16) TFR(24) x0 += ks2; x1 += k0 + 2u;
  TFR(13) TFR(15) TFR(26) TFR(6)  x0 += k0;  x1 += k1 + 3u;
  TFR(17) TFR(29) TFR(16) TFR(24) x0 += k1;  x1 += ks2 + 4u;
  TFR(13) TFR(15) TFR(26) TFR(6)  x0 += ks2; x1 += k0 + 5u;
#undef TFR
  o0 = x0; o1 = x1;
}
__device__ __forceinline__ unsigned jax_bits(unsigned k0, unsigned k1, unsigned m) {
  unsigned o0, o1; tf2x32(k0, k1, 0u, m, o0, o1); return o0 ^ o1;
}

// ---------------- scratch arena ----------------
__device__ __align__(256) unsigned char g_arena[44u * 1024u * 1024u];

// ---------------- global barrier ----------------
__device__ unsigned g_cnt = 0;
__device__ unsigned g_sense = 0;
__device__ __forceinline__ void gbar() {
  __syncthreads();
  if (threadIdx.x == 0) {
    unsigned s = *(volatile unsigned*)&g_sense;
    __threadfence();
    if (atomicAdd(&g_cnt, 1u) == gridDim.x - 1u) {
      g_cnt = 0u;
      __threadfence();
      atomicExch(&g_sense, s + 1u);
    } else {
      while (*(volatile unsigned*)&g_sense == s) __nanosleep(64);
      __threadfence();
    }
  }
  __syncthreads();
}

// ---------------- job structs ----------------
struct GJob { const int* cnt; const int* lst; int cap; const float* H; float* out;
              const float* w; int n; };
struct GemmJob { const float* A[3]; const float* B[3]; float* C;
                 int N, npairs, relu, tStart; };
struct GemmSet { GemmJob j[4]; int njobs; int ntiles; int tileM; };
struct PruneCfg {
  const int* rcnt; const int* rlst; int cap;
  const float* U; const float* V;
  const float* b1; const float* W2; const float* b2;
  int Nc; unsigned k0, k1; int* sel; float* outW;
};
struct Mega {
  const int* key[6]; const int* part[6];
  int* cnt[6]; int* lst[6];
  int pack[6]; int cap[6]; int eStart[7];
  GJob g1[4]; GJob g2[2]; GJob g3[2];
  GemmSet gm1, gm2, gmEP, gm3;
  PruneCfg cp, ca; int nPP, nRows;
  const int* idxPtr; const float* HP0a; const float* HA0a;
  const int* ppcnt; const int* pplst; int ppcap; const float* wpp;
  const int* apcnt; const int* aplst; int apcap;
  const float* Wselfp1; const float* Wpp1a; const float* Wap1a;
  const float* Wc; const float* bc; float* yout;
};

__device__ __forceinline__ unsigned long long packkey(float v, int j) {
  unsigned u = __float_as_uint(v);
  u = (u >> 31) ? ~u : (u | 0x80000000u);
  return (((unsigned long long)u) << 32) |
         (unsigned long long)(0xFFFFFFFFu - (unsigned)j);
}

// ---------------- phase: gather (virtual grid [b0, b0+nb)) ----------------
__device__ void do_gather(const GJob* jobs, int nj, int b0, int nb) {
  int gw = (int)(((blockIdx.x - b0) * blockDim.x + threadIdx.x) >> 5);
  int nw = (int)((nb * blockDim.x) >> 5);
  int lane = threadIdx.x & 31;
  for (int jx = 0; jx < nj; jx++) {
    GJob jb = jobs[jx];
    for (int node = gw; node < jb.n; node += nw) {
      int b = node * jb.cap;
      int deg = jb.cnt[node];
      int e = b + deg;
      float4 acc = make_float4(0.f, 0.f, 0.f, 0.f);
      if (jb.w) {
        int q = b;
        for (; q + 2 <= e; q += 2) {
          int p0 = jb.lst[q], p1 = jb.lst[q + 1];
          float w0 = jb.w[p0 >> 12], w1 = jb.w[p1 >> 12];
          if (w0 != 0.f) {
            int s = p0 & 4095;
            float4 v = *((const float4*)(jb.H + (size_t)s * HD) + lane);
            acc.x += v.x; acc.y += v.y; acc.z += v.z; acc.w += v.w;
          }
          if (w1 != 0.f) {
            int s = p1 & 4095;
            float4 v = *((const float4*)(jb.H + (size_t)s * HD) + lane);
            acc.x += v.x; acc.y += v.y; acc.z += v.z; acc.w += v.w;
          }
        }
        for (; q < e; ++q) {
          int p = jb.lst[q];
          float wt = jb.w[p >> 12];
          if (wt != 0.f) {
            int s = p & 4095;
            float4 v = *((const float4*)(jb.H + (size_t)s * HD) + lane);
            acc.x += v.x; acc.y += v.y; acc.z += v.z; acc.w += v.w;
          }
        }
      } else {
        int q = b;
        for (; q + 4 <= e; q += 4) {
          int s0 = jb.lst[q] & 4095, s1 = jb.lst[q + 1] & 4095;
          int s2 = jb.lst[q + 2] & 4095, s3 = jb.lst[q + 3] & 4095;
          float4 v0 = *((const float4*)(jb.H + (size_t)s0 * HD) + lane);
          float4 v1 = *((const float4*)(jb.H + (size_t)s1 * HD) + lane);
          float4 v2 = *((const float4*)(jb.H + (size_t)s2 * HD) + lane);
          float4 v3 = *((const float4*)(jb.H + (size_t)s3 * HD) + lane);
          acc.x += (v0.x + v1.x) + (v2.x + v3.x);
          acc.y += (v0.y + v1.y) + (v2.y + v3.y);
          acc.z += (v0.z + v1.z) + (v2.z + v3.z);
          acc.w += (v0.w + v1.w) + (v2.w + v3.w);
        }
        for (; q < e; ++q) {
          int s = jb.lst[q] & 4095;
          float4 v = *((const float4*)(jb.H + (size_t)s * HD) + lane);
          acc.x += v.x; acc.y += v.y; acc.z += v.z; acc.w += v.w;
        }
      }
      float inv = 1.f / fmaxf((float)deg, 1.f);
      acc.x *= inv; acc.y *= inv; acc.z *= inv; acc.w *= inv;
      *((float4*)(jb.out + (size_t)node * HD) + lane) = acc;
    }
  }
}

// ---------------- phase: gemm (RPT*16 x 64 tiles, virtual grid) ----------------
template <int RPT>
__device__ void gemm_body(const GemmSet& gs, float* smf, int b0, int nb) {
  float (*As)[68] = (float(*)[68])smf;
  float (*Bs)[68] = (float(*)[68])(smf + 16 * 68);
  const int TM = RPT * 16;
  int tid = threadIdx.x;
  int ty = tid >> 4, tx = tid & 15;
  for (int tile = blockIdx.x - b0; tile < gs.ntiles; tile += nb) {
    int ji = 0;
    while (ji + 1 < gs.njobs && tile >= gs.j[ji + 1].tStart) ji++;
    GemmJob jb = gs.j[ji];
    int local = tile - jb.tStart;
    int ct = jb.N >> 6;
    int row0 = (local / ct) * TM;
    int col0 = (local % ct) * 64;
    unsigned long long acc[RPT][2];
#pragma unroll
    for (int i = 0; i < RPT; i++)
#pragma unroll
      for (int j = 0; j < 2; j++) acc[i][j] = 0ull;
    for (int p = 0; p < jb.npairs; p++) {
      const float* A = jb.A[p];
      const float* B = jb.B[p];
      for (int kt = 0; kt < 128; kt += 16) {
        if (RPT == 4) {
          int m = tid >> 2, kk = (tid & 3) * 4;
          float4 v = *(const float4*)(A + (size_t)(row0 + m) * 128 + kt + kk);
          As[kk][m] = v.x; As[kk + 1][m] = v.y; As[kk + 2][m] = v.z; As[kk + 3][m] = v.w;
        } else {
          int m = tid >> 3, kk = (tid & 7) * 2;
          float2 v = *(const float2*)(A + (size_t)(row0 + m) * 128 + kt + kk);
          As[kk][m] = v.x; As[kk + 1][m] = v.y;
        }
        {
          int kk = tid >> 4, n4 = (tid & 15) * 4;
          float4 v = *(const float4*)(B + (size_t)(kt + kk) * jb.N + col0 + n4);
          Bs[kk][n4] = v.x; Bs[kk][n4 + 1] = v.y; Bs[kk][n4 + 2] = v.z; Bs[kk][n4 + 3] = v.w;
        }
        __syncthreads();
#pragma unroll
        for (int k = 0; k < 16; k++) {
          unsigned long long a2[RPT], b2[2];
#pragma unroll
          for (int i = 0; i < RPT; i++) {
            unsigned ai = __float_as_uint(As[k][ty * RPT + i]);
            asm("mov.b64 %0, {%1, %1};" : "=l"(a2[i]) : "r"(ai));
          }
#pragma unroll
          for (int j = 0; j < 2; j++)
            b2[j] = *(const unsigned long long*)&Bs[k][tx * 4 + j * 2];
#pragma unroll
          for (int i = 0; i < RPT; i++)
#pragma unroll
            for (int j = 0; j < 2; j++)
              asm("fma.rn.f32x2 %0, %1, %2, %0;" : "+l"(acc[i][j])
                  : "l"(a2[i]), "l"(b2[j]));
        }
        __syncthreads();
      }
    }
#pragma unroll
    for (int i = 0; i < RPT; i++) {
      int row = row0 + ty * RPT + i;
#pragma unroll
      for (int j = 0; j < 2; j++) {
        unsigned u0, u1;
        asm("mov.b64 {%0, %1}, %2;" : "=r"(u0), "=r"(u1) : "l"(acc[i][j]));
        float c0 = __uint_as_float(u0), c1 = __uint_as_float(u1);
        if (jb.relu) { c0 = fmaxf(c0, 0.f); c1 = fmaxf(c1, 0.f); }
        float2* cp = (float2*)(jb.C + (size_t)row * jb.N + col0 + tx * 4 + j * 2);
        *cp = make_float2(c0, c1);
      }
    }
  }
}
__device__ void do_gemm(const GemmSet& gs, float* smf, int b0, int nb) {
  if (gs.tileM == 32) gemm_body<2>(gs, smf, b0, nb);
  else                gemm_body<4>(gs, smf, b0, nb);
}

// ---------------- phase: prune (row loop) ----------------
__device__ void do_prune(const Mega& M, float* smf) {
  __shared__ int sel5[5];
  __shared__ int ncand;
  int t = threadIdx.x, warp = t >> 5, lane = t & 31;
  for (int row = blockIdx.x; row < M.nRows; row += gridDim.x) {
    PruneCfg cfg = (row < M.nPP) ? M.cp : M.ca;
    int i = (row < M.nPP) ? row : row - M.nPP;
    __syncthreads();
    if (t == 0) ncand = 0;
    float* Arow = smf;
    float* Urow = smf + cfg.Nc;
    float* W2c  = Urow + 256;
    unsigned long long* cand = (unsigned long long*)(W2c + 256);
    Urow[t] = cfg.U[(size_t)i * 256 + t] + cfg.b1[t];
    W2c[t] = cfg.W2[2 * t];
    {
      float4* Az = (float4*)Arow;
      int n4 = cfg.Nc >> 2;
      for (int j = t; j < n4; j += 256) Az[j] = make_float4(0.f, 0.f, 0.f, 0.f);
    }
    __syncthreads();

    int b = i * cfg.cap, nE = cfg.rcnt[i];
    float b2v = cfg.b2[0];
    const float4* U4 = (const float4*)&Urow[lane * 8];
    const float4* W4 = (const float4*)&W2c[lane * 8];
    float4 u0 = U4[0], u1 = U4[1], w0 = W4[0], w1 = W4[1];
    for (int e = warp; e < nE; e += 16) {
      int p1 = cfg.rlst[b + e];
      int d1 = p1 & 4095;
      int e2 = e + 8;
      bool has2 = (e2 < nE);
      int p2 = has2 ? cfg.rlst[b + e2] : p1;
      int d2 = p2 & 4095;
      const float4* V1 = (const float4*)(cfg.V + (size_t)d1 * 256) + lane * 2;
      const float4* V2 = (const float4*)(cfg.V + (size_t)d2 * 256) + lane * 2;
      float4 a0 = V1[0], a1 = V1[1];
      float4 c0 = V2[0], c1 = V2[1];
      float acc1 = fmaxf(u0.x + a0.x, 0.f) * w0.x + fmaxf(u0.y + a0.y, 0.f) * w0.y +
                   fmaxf(u0.z + a0.z, 0.f) * w0.z + fmaxf(u0.w + a0.w, 0.f) * w0.w +
                   fmaxf(u1.x + a1.x, 0.f) * w1.x + fmaxf(u1.y + a1.y, 0.f) * w1.y +
                   fmaxf(u1.z + a1.z, 0.f) * w1.z + fmaxf(u1.w + a1.w, 0.f) * w1.w;
      float acc2 = fmaxf(u0.x + c0.x, 0.f) * w0.x + fmaxf(u0.y + c0.y, 0.f) * w0.y +
                   fmaxf(u0.z + c0.z, 0.f) * w0.z + fmaxf(u0.w + c0.w, 0.f) * w0.w +
                   fmaxf(u1.x + c1.x, 0.f) * w1.x + fmaxf(u1.y + c1.y, 0.f) * w1.y +
                   fmaxf(u1.z + c1.z, 0.f) * w1.z + fmaxf(u1.w + c1.w, 0.f) * w1.w;
#pragma unroll
      for (int o = 16; o; o >>= 1) {
        acc1 += __shfl_xor_sync(0xffffffffu, acc1, o);
        acc2 += __shfl_xor_sync(0xffffffffu, acc2, o);
      }
      if (lane == 0) {
        atomicAdd(&Arow[d1], acc1 + b2v);
        if (has2) atomicAdd(&Arow[d2], acc2 + b2v);
      }
    }
    __syncthreads();

    {
      const float4* Az = (const float4*)Arow;
      int n4 = cfg.Nc >> 2;
      for (int j4 = t; j4 < n4; j4 += 256) {
        float4 a = Az[j4];
        if (a.x > 0.f || a.y > 0.f || a.z > 0.f || a.w > 0.f) {
          float av[4] = {a.x, a.y, a.z, a.w};
#pragma unroll
          for (int c = 0; c < 4; c++) {
            if (av[c] > 0.f) {
              int j = j4 * 4 + c;
              unsigned m = (unsigned)i * (unsigned)cfg.Nc + (unsigned)j;
              unsigned bits = jax_bits(cfg.k0, cfg.k1, m);
              float f = __uint_as_float((bits >> 9) | 0x3f800000u) - 1.0f;
              float u = fmaxf(1e-10f, f + 1e-10f);
              float y = av[c] + (-logf(-logf(u)));
              int pos = atomicAdd(&ncand, 1);
              if (pos < CANDMAX) cand[pos] = packkey(y, j);
            }
          }
        }
      }
    }
    __syncthreads();
    int nc = ncand < CANDMAX ? ncand : CANDMAX;

    if (warp == 0) {
      unsigned long long prev = 0;
      for (int r = 0; r < 5; r++) {
        unsigned long long best = 0ull;
        for (int q = lane; q < nc; q += 32) {
          unsigned long long k = cand[q];
          if (k == prev) { cand[q] = 0ull; k = 0ull; }
          if (k > best) best = k;
        }
#pragma unroll
        for (int o = 16; o; o >>= 1) {
          unsigned long long v = __shfl_xor_sync(0xffffffffu, best, o);
          if (v > best) best = v;
        }
        if (lane == 0)
          sel5[r] = (best != 0ull)
                        ? (int)(0xFFFFFFFFu - (unsigned)(best & 0xFFFFFFFFull))
                        : -1;
        prev = best;
      }
      if (lane == 0) {
        int r = 0;
        while (r < 5 && sel5[r] >= 0) r++;
        for (int j = 0; j < cfg.Nc && r < 5; j++)
          if (!(Arow[j] > 0.f)) sel5[r++] = j;
        for (int q = 0; q < 5; q++) cfg.sel[i * 5 + q] = sel5[q];
      }
    }
    __syncthreads();

    int s0 = sel5[0], s1 = sel5[1], s2 = sel5[2], s3 = sel5[3], s4 = sel5[4];
    for (int e = t; e < nE; e += 256) {
      int p = cfg.rlst[b + e];
      int d = p & 4095;
      int eid = p >> 12;
      cfg.outW[eid] = (d == s0 || d == s1 || d == s2 || d == s3 || d == s4) ? 1.f : 0.f;
    }
  }
}

// ---------------- phase: node_out (block 0) ----------------
__device__ void do_node_out(const Mega& M, float* smf) {
  float* selfv = smf;
  float* mpp = smf + 128;
  float* mapv = smf + 256;
  float* agg = smf + 384;
  int t = threadIdx.x;
  int idx = M.idxPtr[0];
  if (t < 128) {
    selfv[t] = M.HP0a[(size_t)idx * HD + t];
    int b = idx * M.ppcap, nE = M.ppcnt[idx];
    float s = 0.f;
    for (int q = b; q < b + nE; q++) {
      int p = M.pplst[q];
      if (M.wpp[p >> 12] != 0.f) s += M.HP0a[(size_t)(p & 4095) * HD + t];
    }
    mpp[t] = s / fmaxf((float)nE, 1.f);
    b = idx * M.apcap; nE = M.apcnt[idx];
    s = 0.f;
    for (int q = b; q < b + nE; q++)
      s += M.HA0a[(size_t)(M.aplst[q] & 4095) * HD + t];
    mapv[t] = s / fmaxf((float)nE, 1.f);
  }
  __syncthreads();
  if (t < 128) {
    float a = 0.f;
    for (int k = 0; k < HD; k++)
      a += selfv[k] * M.Wselfp1[k * HD + t] + mpp[k] * M.Wpp1a[k * HD + t] +
           mapv[k] * M.Wap1a[k * HD + t];
    agg[t] = fmaxf(a, 0.f);
  }
  __syncthreads();
  if (t < 5) {
    float y = M.bc[t];
    for (int k = 0; k < HD; k++) y += agg[k] * M.Wc[k * 5 + t];
    M.yout[t] = y;
  }
}

// ---------------- the megakernel ----------------
__global__ __launch_bounds__(256, 4) void mega_kernel(Mega M) {
  extern __shared__ float smf[];
  int t = threadIdx.x;
  // P1: single-pass bucket fill (x8); CNT pre-zeroed by tail of prior launch
  {
    int tot8 = M.eStart[6] >> 3;
    for (int g = blockIdx.x * 256 + t; g < tot8; g += gridDim.x * 256) {
      int g8 = g * 8;
      int r = 0;
      while (g8 >= M.eStart[r + 1]) r++;
      int e = g8 - M.eStart[r];
      int4 ka = *(const int4*)(M.key[r] + e);
      int4 kb = *(const int4*)(M.key[r] + e + 4);
      int4 pa = *(const int4*)(M.part[r] + e);
      int4 pb = *(const int4*)(M.part[r] + e + 4);
      int pk = M.pack[r];
      int cap = M.cap[r];
      int* cnt = M.cnt[r];
      int* out = M.lst[r];
#define DOF(K, P, EE) { int pos = atomicAdd(&cnt[K], 1); \
      out[(K) * cap + pos] = (P) | (pk ? ((EE) << 12) : 0); }
      DOF(ka.x, pa.x, e)     DOF(ka.y, pa.y, e + 1)
      DOF(ka.z, pa.z, e + 2) DOF(ka.w, pa.w, e + 3)
      DOF(kb.x, pb.x, e + 4) DOF(kb.y, pb.y, e + 5)
      DOF(kb.z, pb.z, e + 6) DOF(kb.w, pb.w, e + 7)
#undef DOF
    }
  }
  gbar();
  do_gather(M.g1, 2, 0, gridDim.x);
  gbar();
  {
    int split = (gridDim.x > 384) ? 192 : (gridDim.x >> 1);
    if (blockIdx.x < split) do_gemm(M.gm1, smf, 0, split);
    else                    do_gather(M.g1 + 2, 2, split, gridDim.x - split);
  }
  gbar();
  do_gather(M.g2, 2, 0, gridDim.x);  gbar();
  do_gemm(M.gm2, smf, 0, gridDim.x); gbar();
  do_gemm(M.gmEP, smf, 0, gridDim.x); gbar();
  do_prune(M, smf);                  gbar();
  do_gather(M.g3, 2, 0, gridDim.x);  gbar();
  do_gemm(M.gm3, smf, 0, gridDim.x); gbar();
  if (blockIdx.x == 0) {
    do_node_out(M, smf);
    __syncthreads();
    for (int i = t; i < 4096; i += 256) { M.cnt[0][i] = 0; M.cnt[5][i] = 0; }
  } else {
    for (int i = (blockIdx.x - 1) * 256 + t; i < 4 * 4096;
         i += (gridDim.x - 1) * 256)
      M.cnt[1 + (i >> 12)][i & 4095] = 0;
  }
}

// ---------------- host launcher ----------------
extern "C" void kernel_launch(void* const* d_in, const int* in_sizes, int n_in,
                              void* d_out, int out_size) {
  const float* x_p = (const float*)d_in[0];
  const float* x_a = (const float*)d_in[1];
  const int* ei_pp = (const int*)d_in[2];
  const int* ei_aa = (const int*)d_in[3];
  const int* ei_pa = (const int*)d_in[4];
  const int* ei_ap = (const int*)d_in[5];
  const int* idxPtr = (const int*)d_in[8];
  const float* Ws_p0 = (const float*)d_in[9];
  const float* Ws_p1 = (const float*)d_in[10];
  const float* Ws_a0 = (const float*)d_in[11];
  const float* Ws_a1 = (const float*)d_in[12];
  const float* Wpp0 = (const float*)d_in[13];
  const float* Wpp1 = (const float*)d_in[14];
  const float* Waa0 = (const float*)d_in[15];
  const float* Waa1 = (const float*)d_in[16];
  const float* Wpa0 = (const float*)d_in[17];
  const float* Wap0 = (const float*)d_in[19];
  const float* Wap1 = (const float*)d_in[20];
  const float* Wep1_pp = (const float*)d_in[21];
  const float* bep1_pp = (const float*)d_in[22];
  const float* Wep2_pp = (const float*)d_in[23];
  const float* bep2_pp = (const float*)d_in[24];
  const float* Wep1_aa = (const float*)d_in[25];
  const float* bep1_aa = (const float*)d_in[26];
  const float* Wep2_aa = (const float*)d_in[27];
  const float* bep2_aa = (const float*)d_in[28];
  const float* Wc = (const float*)d_in[29];
  const float* bc = (const float*)d_in[30];

  int Epp = in_sizes[2] / 2, Eaa = in_sizes[3] / 2;
  int Epa = in_sizes[4] / 2, Eap = in_sizes[5] / 2;
  const int* pp_src = ei_pp;  const int* pp_dst = ei_pp + Epp;
  const int* aa_src = ei_aa;  const int* aa_dst = ei_aa + Eaa;
  const int* pa_src = ei_pa;  const int* pa_dst = ei_pa + Epa;
  const int* ap_src = ei_ap;  const int* ap_dst = ei_ap + Eap;

  unsigned kpp0, kpp1, kaa0, kaa1;
  tf2x32(0u, 42u, 0u, 0u, kpp0, kpp1);
  tf2x32(0u, 42u, 0u, 1u, kaa0, kaa1);

  void* basep = nullptr;
  cudaGetSymbolAddress(&basep, g_arena);
  unsigned char* ar = (unsigned char*)basep;
  size_t off = 0;
  auto carve = [&](size_t bytes) -> unsigned char* {
    unsigned char* p = ar + off;
    off += (bytes + 255) & ~(size_t)255;
    return p;
  };
  float* AGGP  = (float*)carve((size_t)NPAP * HD * 4);
  float* AGGA  = (float*)carve((size_t)NAUT * HD * 4);
  float* AGGP2 = (float*)carve((size_t)NPAP * HD * 4);
  float* AGGA2 = (float*)carve((size_t)NAUT * HD * 4);
  float* HP0 = (float*)carve((size_t)NPAP * HD * 4);
  float* HP1 = (float*)carve((size_t)NPAP * HD * 4);
  float* HA0 = (float*)carve((size_t)NAUT * HD * 4);
  float* HA1 = (float*)carve((size_t)NAUT * HD * 4);
  float* UP = (float*)carve((size_t)NPAP * 256 * 4);
  float* VP = (float*)carve((size_t)NPAP * 256 * 4);
  float* UA = (float*)carve((size_t)NAUT * 256 * 4);
  float* VA = (float*)carve((size_t)NAUT * 256 * 4);
  int* CNT = (int*)carve(6 * 4096 * 4);
  int* P0 = (int*)carve((size_t)NPAP * 128 * 4);
  int* P1 = (int*)carve((size_t)NPAP * 128 * 4);
  int* P2 = (int*)carve((size_t)NAUT * 128 * 4);
  int* P3 = (int*)carve((size_t)NAUT * 128 * 4);
  int* P4 = (int*)carve((size_t)NAUT * 256 * 4);
  int* P5 = (int*)carve((size_t)NPAP * 128 * 4);
  int* SELPP = (int*)carve((size_t)NPAP * 5 * 4);
  int* SELAA = (int*)carve((size_t)NAUT * 5 * 4);

  float* out_f = (float*)d_out;
  float* WPPo = out_f + 5;
  float* WAAo = out_f + 5 + Epp;

  Mega M;
  const int* keys[6]  = {pp_dst, pp_src, aa_dst, aa_src, pa_dst, ap_dst};
  const int* parts[6] = {pp_src, pp_dst, aa_src, aa_dst, pa_src, ap_src};
  int Es[6] = {Epp, Epp, Eaa, Eaa, Epa, Eap};
  int packs[6] = {1, 1, 1, 1, 0, 0};
  int caps[6] = {128, 128, 128, 128, 256, 128};
  int* lsts[6] = {P0, P1, P2, P3, P4, P5};
  int run = 0;
  for (int r = 0; r < 6; r++) {
    M.key[r] = keys[r]; M.part[r] = parts[r];
    M.cnt[r] = CNT + r * 4096; M.lst[r] = lsts[r];
    M.pack[r] = packs[r]; M.cap[r] = caps[r];
    M.eStart[r] = run; run += Es[r];
  }
  M.eStart[6] = run;

  M.g1[0] = {CNT + 0 * 4096, P0, 128, x_p, AGGP, nullptr, NPAP};
  M.g1[1] = {CNT + 2 * 4096, P2, 128, x_a, AGGA, nullptr, NAUT};
  M.g1[2] = {CNT + 5 * 4096, P5, 128, x_a, AGGP2, nullptr, NPAP};
  M.g1[3] = {CNT + 4 * 4096, P4, 256, x_p, AGGA2, nullptr, NAUT};
  M.g2[0] = {CNT + 0 * 4096, P0, 128, HP0, AGGP, nullptr, NPAP};
  M.g2[1] = {CNT + 2 * 4096, P2, 128, HA0, AGGA, nullptr, NAUT};
  M.g3[0] = {CNT + 0 * 4096, P0, 128, x_p, AGGP, WPPo, NPAP};
  M.g3[1] = {CNT + 2 * 4096, P2, 128, x_a, AGGA, WAAo, NAUT};

  // gm1/gm2/gm3: 32x64 tiles -> 384 tiles; EP stays 64x64 -> 768 tiles
  M.gm1.njobs = 2; M.gm1.ntiles = 384; M.gm1.tileM = 32;
  M.gm1.j[0] = {{x_p, AGGP, nullptr}, {Ws_p0, Wpp0, nullptr}, HP0, 128, 2, 1, 0};
  M.gm1.j[1] = {{x_a, AGGA, nullptr}, {Ws_a0, Waa0, nullptr}, HA0, 128, 2, 1, 256};
  M.gm2.njobs = 2; M.gm2.ntiles = 384; M.gm2.tileM = 32;
  M.gm2.j[0] = {{HP0, AGGP, nullptr}, {Ws_p1, Wpp1, nullptr}, HP1, 128, 2, 1, 0};
  M.gm2.j[1] = {{HA0, AGGA, nullptr}, {Ws_a1, Waa1, nullptr}, HA1, 128, 2, 1, 256};
  M.gmEP.njobs = 4; M.gmEP.ntiles = 768; M.gmEP.tileM = 64;
  M.gmEP.j[0] = {{HP1, nullptr, nullptr}, {Wep1_pp, nullptr, nullptr}, UP, 256, 1, 0, 0};
  M.gmEP.j[1] = {{HP1, nullptr, nullptr}, {Wep1_pp + 128 * 256, nullptr, nullptr}, VP, 256, 1, 0, 256};
  M.gmEP.j[2] = {{HA1, nullptr, nullptr}, {Wep1_aa, nullptr, nullptr}, UA, 256, 1, 0, 512};
  M.gmEP.j[3] = {{HA1, nullptr, nullptr}, {Wep1_aa + 128 * 256, nullptr, nullptr}, VA, 256, 1, 0, 640};
  M.gm3.njobs = 2; M.gm3.ntiles = 384; M.gm3.tileM = 32;
  M.gm3.j[0] = {{x_p, AGGP, AGGP2}, {Ws_p0, Wpp0, Wap0}, HP0, 128, 3, 1, 0};
  M.gm3.j[1] = {{x_a, AGGA, AGGA2}, {Ws_a0, Waa0, Wpa0}, HA0, 128, 3, 1, 256};

  M.cp = {CNT + 1 * 4096, P1, 128, UP, VP, bep1_pp, Wep2_pp, bep2_pp,
          4096, kpp0, kpp1, SELPP, WPPo};
  M.ca = {CNT + 3 * 4096, P3, 128, UA, VA, bep1_aa, Wep2_aa, bep2_aa,
          2048, kaa0, kaa1, SELAA, WAAo};
  M.nPP = NPAP; M.nRows = NPAP + NAUT;

  M.idxPtr = idxPtr; M.HP0a = HP0; M.HA0a = HA0;
  M.ppcnt = CNT + 0 * 4096; M.pplst = P0; M.ppcap = 128; M.wpp = WPPo;
  M.apcnt = CNT + 5 * 4096; M.aplst = P5; M.apcap = 128;
  M.Wselfp1 = Ws_p1; M.Wpp1a = Wpp1; M.Wap1a = Wap1;
  M.Wc = Wc; M.bc = bc; M.yout = out_f;

  int nsm = 148;
  cudaDeviceGetAttribute(&nsm, cudaDevAttrMultiProcessorCount, 0);
  int occ = 0;
  cudaOccupancyMaxActiveBlocksPerMultiprocessor(&occ, mega_kernel, 256, SMEMB);
  if (occ < 1) occ = 1;
  long long grid = (long long)occ * nsm;
  if (grid > 1024) grid = 1024;
  mega_kernel<<<(int)grid, 256, SMEMB>>>(M);
}

// round 17
// speedup vs baseline: 1.1828x; 1.1828x over previous
#include <cuda_runtime.h>
#include <cstdint>

#define NPAP 4096
#define NAUT 2048
#define HD   128
#define CANDMAX 1024
#define SMEMB 27136

// ---------------- threefry2x32 (JAX, 20 rounds) ----------------
__host__ __device__ __forceinline__ void tf2x32(unsigned k0, unsigned k1,
                                                unsigned x0, unsigned x1,
                                                unsigned &o0, unsigned &o1) {
  unsigned ks2 = k0 ^ k1 ^ 0x1BD11BDAu;
  x0 += k0; x1 += k1;
#define TFR(r) { x0 += x1; x1 = (x1 << (r)) | (x1 >> (32 - (r))); x1 ^= x0; }
  TFR(13) TFR(15) TFR(26) TFR(6)  x0 += k1;  x1 += ks2 + 1u;
  TFR(17) TFR(29) TFR(16) TFR(24) x0 += ks2; x1 += k0 + 2u;
  TFR(13) TFR(15) TFR(26) TFR(6)  x0 += k0;  x1 += k1 + 3u;
  TFR(17) TFR(29) TFR(16) TFR(24) x0 += k1;  x1 += ks2 + 4u;
  TFR(13) TFR(15) TFR(26) TFR(6)  x0 += ks2; x1 += k0 + 5u;
#undef TFR
  o0 = x0; o1 = x1;
}
__device__ __forceinline__ unsigned jax_bits(unsigned k0, unsigned k1, unsigned m) {
  unsigned o0, o1; tf2x32(k0, k1, 0u, m, o0, o1); return o0 ^ o1;
}

// ---------------- scratch arena ----------------
__device__ __align__(256) unsigned char g_arena[44u * 1024u * 1024u];

// ---------------- global barrier ----------------
__device__ unsigned g_cnt = 0;
__device__ unsigned g_sense = 0;
__device__ __forceinline__ void gbar() {
  __syncthreads();
  if (threadIdx.x == 0) {
    unsigned s = *(volatile unsigned*)&g_sense;
    __threadfence();
    if (atomicAdd(&g_cnt, 1u) == gridDim.x - 1u) {
      g_cnt = 0u;
      __threadfence();
      atomicExch(&g_sense, s + 1u);
    } else {
      while (*(volatile unsigned*)&g_sense == s) __nanosleep(64);
      __threadfence();
    }
  }
  __syncthreads();
}

// ---------------- job structs ----------------
struct GJob { const int* cnt; const int* lst; int cap; const float* H; float* out;
              const float* w; int n; };
struct GemmJob { const float* A[3]; const float* B[3]; float* C;
                 int N, npairs, relu, tStart; };
struct GemmSet { GemmJob j[4]; int njobs; int ntiles; };
struct PruneCfg {
  const int* rcnt; const int* rlst; int cap;
  const float* U; const float* V;
  const float* b1; const float* W2; const float* b2;
  int Nc; unsigned k0, k1; int* sel; float* outW;
};
struct Mega {
  const int* key[6]; const int* part[6];
  int* cnt[6]; int* lst[6];
  int pack[6]; int cap[6]; int eStart[7];
  GJob g1[4]; GJob g2[2]; GJob g3[2];
  GemmSet gm1, gm2, gmEP, gm3;
  PruneCfg cp, ca; int nPP, nRows;
  const int* idxPtr; const float* HP0a; const float* HA0a;
  const int* ppcnt; const int* pplst; int ppcap; const float* wpp;
  const int* apcnt; const int* aplst; int apcap;
  const float* Wselfp1; const float* Wpp1a; const float* Wap1a;
  const float* Wc; const float* bc; float* yout;
};

__device__ __forceinline__ unsigned long long packkey(float v, int j) {
  unsigned u = __float_as_uint(v);
  u = (u >> 31) ? ~u : (u | 0x80000000u);
  return (((unsigned long long)u) << 32) |
         (unsigned long long)(0xFFFFFFFFu - (unsigned)j);
}

// ---------------- phase: gather (virtual grid [b0, b0+nb)) ----------------
__device__ void do_gather(const GJob* jobs, int nj, int b0, int nb) {
  int gw = (int)(((blockIdx.x - b0) * blockDim.x + threadIdx.x) >> 5);
  int nw = (int)((nb * blockDim.x) >> 5);
  int lane = threadIdx.x & 31;
  for (int jx = 0; jx < nj; jx++) {
    GJob jb = jobs[jx];
    for (int node = gw; node < jb.n; node += nw) {
      int b = node * jb.cap;
      int deg = jb.cnt[node];
      int e = b + deg;
      float4 acc = make_float4(0.f, 0.f, 0.f, 0.f);
      if (jb.w) {
        int q = b;
        for (; q + 2 <= e; q += 2) {
          int p0 = jb.lst[q], p1 = jb.lst[q + 1];
          float w0 = jb.w[p0 >> 12], w1 = jb.w[p1 >> 12];
          if (w0 != 0.f) {
            int s = p0 & 4095;
            float4 v = *((const float4*)(jb.H + (size_t)s * HD) + lane);
            acc.x += v.x; acc.y += v.y; acc.z += v.z; acc.w += v.w;
          }
          if (w1 != 0.f) {
            int s = p1 & 4095;
            float4 v = *((const float4*)(jb.H + (size_t)s * HD) + lane);
            acc.x += v.x; acc.y += v.y; acc.z += v.z; acc.w += v.w;
          }
        }
        for (; q < e; ++q) {
          int p = jb.lst[q];
          float wt = jb.w[p >> 12];
          if (wt != 0.f) {
            int s = p & 4095;
            float4 v = *((const float4*)(jb.H + (size_t)s * HD) + lane);
            acc.x += v.x; acc.y += v.y; acc.z += v.z; acc.w += v.w;
          }
        }
      } else {
        int q = b;
        for (; q + 4 <= e; q += 4) {
          int s0 = jb.lst[q] & 4095, s1 = jb.lst[q + 1] & 4095;
          int s2 = jb.lst[q + 2] & 4095, s3 = jb.lst[q + 3] & 4095;
          float4 v0 = *((const float4*)(jb.H + (size_t)s0 * HD) + lane);
          float4 v1 = *((const float4*)(jb.H + (size_t)s1 * HD) + lane);
          float4 v2 = *((const float4*)(jb.H + (size_t)s2 * HD) + lane);
          float4 v3 = *((const float4*)(jb.H + (size_t)s3 * HD) + lane);
          acc.x += (v0.x + v1.x) + (v2.x + v3.x);
          acc.y += (v0.y + v1.y) + (v2.y + v3.y);
          acc.z += (v0.z + v1.z) + (v2.z + v3.z);
          acc.w += (v0.w + v1.w) + (v2.w + v3.w);
        }
        for (; q < e; ++q) {
          int s = jb.lst[q] & 4095;
          float4 v = *((const float4*)(jb.H + (size_t)s * HD) + lane);
          acc.x += v.x; acc.y += v.y; acc.z += v.z; acc.w += v.w;
        }
      }
      float inv = 1.f / fmaxf((float)deg, 1.f);
      acc.x *= inv; acc.y *= inv; acc.z *= inv; acc.w *= inv;
      *((float4*)(jb.out + (size_t)node * HD) + lane) = acc;
    }
  }
}

// ---------------- phase: gemm (64x64 tiles, virtual grid) ----------------
__device__ void do_gemm(const GemmSet& gs, float* smf, int b0, int nb) {
  float (*As)[68] = (float(*)[68])smf;
  float (*Bs)[68] = (float(*)[68])(smf + 16 * 68);
  int tid = threadIdx.x;
  int ty = tid >> 4, tx = tid & 15;
  for (int tile = blockIdx.x - b0; tile < gs.ntiles; tile += nb) {
    int ji = 0;
    while (ji + 1 < gs.njobs && tile >= gs.j[ji + 1].tStart) ji++;
    GemmJob jb = gs.j[ji];
    int local = tile - jb.tStart;
    int ct = jb.N >> 6;
    int row0 = (local / ct) * 64;
    int col0 = (local % ct) * 64;
    unsigned long long acc[4][2];
#pragma unroll
    for (int i = 0; i < 4; i++)
#pragma unroll
      for (int j = 0; j < 2; j++) acc[i][j] = 0ull;
    for (int p = 0; p < jb.npairs; p++) {
      const float* A = jb.A[p];
      const float* B = jb.B[p];
      for (int kt = 0; kt < 128; kt += 16) {
        {
          int m = tid >> 2, kk = (tid & 3) * 4;
          float4 v = *(const float4*)(A + (size_t)(row0 + m) * 128 + kt + kk);
          As[kk][m] = v.x; As[kk + 1][m] = v.y; As[kk + 2][m] = v.z; As[kk + 3][m] = v.w;
        }
        {
          int kk = tid >> 4, n4 = (tid & 15) * 4;
          float4 v = *(const float4*)(B + (size_t)(kt + kk) * jb.N + col0 + n4);
          Bs[kk][n4] = v.x; Bs[kk][n4 + 1] = v.y; Bs[kk][n4 + 2] = v.z; Bs[kk][n4 + 3] = v.w;
        }
        __syncthreads();
#pragma unroll
        for (int k = 0; k < 16; k++) {
          unsigned long long a2[4], b2[2];
#pragma unroll
          for (int i = 0; i < 4; i++) {
            unsigned ai = __float_as_uint(As[k][ty * 4 + i]);
            asm("mov.b64 %0, {%1, %1};" : "=l"(a2[i]) : "r"(ai));
          }
#pragma unroll
          for (int j = 0; j < 2; j++)
            b2[j] = *(const unsigned long long*)&Bs[k][tx * 4 + j * 2];
#pragma unroll
          for (int i = 0; i < 4; i++)
#pragma unroll
            for (int j = 0; j < 2; j++)
              asm("fma.rn.f32x2 %0, %1, %2, %0;" : "+l"(acc[i][j])
                  : "l"(a2[i]), "l"(b2[j]));
        }
        __syncthreads();
      }
    }
#pragma unroll
    for (int i = 0; i < 4; i++) {
      int row = row0 + ty * 4 + i;
#pragma unroll
      for (int j = 0; j < 2; j++) {
        unsigned u0, u1;
        asm("mov.b64 {%0, %1}, %2;" : "=r"(u0), "=r"(u1) : "l"(acc[i][j]));
        float c0 = __uint_as_float(u0), c1 = __uint_as_float(u1);
        if (jb.relu) { c0 = fmaxf(c0, 0.f); c1 = fmaxf(c1, 0.f); }
        float2* cp = (float2*)(jb.C + (size_t)row * jb.N + col0 + tx * 4 + j * 2);
        *cp = make_float2(c0, c1);
      }
    }
  }
}

// ---------------- phase: prune (row loop) ----------------
__device__ void do_prune(const Mega& M, float* smf) {
  __shared__ int sel5[5];
  __shared__ int ncand;
  int t = threadIdx.x, warp = t >> 5, lane = t & 31;
  for (int row = blockIdx.x; row < M.nRows; row += gridDim.x) {
    PruneCfg cfg = (row < M.nPP) ? M.cp : M.ca;
    int i = (row < M.nPP) ? row : row - M.nPP;
    __syncthreads();
    if (t == 0) ncand = 0;
    float* Arow = smf;
    float* Urow = smf + cfg.Nc;
    float* W2c  = Urow + 256;
    unsigned long long* cand = (unsigned long long*)(W2c + 256);
    Urow[t] = cfg.U[(size_t)i * 256 + t] + cfg.b1[t];
    W2c[t] = cfg.W2[2 * t];
    {
      float4* Az = (float4*)Arow;
      int n4 = cfg.Nc >> 2;
      for (int j = t; j < n4; j += 256) Az[j] = make_float4(0.f, 0.f, 0.f, 0.f);
    }
    __syncthreads();

    int b = i * cfg.cap, nE = cfg.rcnt[i];
    float b2v = cfg.b2[0];
    const float4* U4 = (const float4*)&Urow[lane * 8];
    const float4* W4 = (const float4*)&W2c[lane * 8];
    float4 u0 = U4[0], u1 = U4[1], w0 = W4[0], w1 = W4[1];
    for (int e = warp; e < nE; e += 16) {
      int p1 = cfg.rlst[b + e];
      int d1 = p1 & 4095;
      int e2 = e + 8;
      bool has2 = (e2 < nE);
      int p2 = has2 ? cfg.rlst[b + e2] : p1;
      int d2 = p2 & 4095;
      const float4* V1 = (const float4*)(cfg.V + (size_t)d1 * 256) + lane * 2;
      const float4* V2 = (const float4*)(cfg.V + (size_t)d2 * 256) + lane * 2;
      float4 a0 = V1[0], a1 = V1[1];
      float4 c0 = V2[0], c1 = V2[1];
      float acc1 = fmaxf(u0.x + a0.x, 0.f) * w0.x + fmaxf(u0.y + a0.y, 0.f) * w0.y +
                   fmaxf(u0.z + a0.z, 0.f) * w0.z + fmaxf(u0.w + a0.w, 0.f) * w0.w +
                   fmaxf(u1.x + a1.x, 0.f) * w1.x + fmaxf(u1.y + a1.y, 0.f) * w1.y +
                   fmaxf(u1.z + a1.z, 0.f) * w1.z + fmaxf(u1.w + a1.w, 0.f) * w1.w;
      float acc2 = fmaxf(u0.x + c0.x, 0.f) * w0.x + fmaxf(u0.y + c0.y, 0.f) * w0.y +
                   fmaxf(u0.z + c0.z, 0.f) * w0.z + fmaxf(u0.w + c0.w, 0.f) * w0.w +
                   fmaxf(u1.x + c1.x, 0.f) * w1.x + fmaxf(u1.y + c1.y, 0.f) * w1.y +
                   fmaxf(u1.z + c1.z, 0.f) * w1.z + fmaxf(u1.w + c1.w, 0.f) * w1.w;
#pragma unroll
      for (int o = 16; o; o >>= 1) {
        acc1 += __shfl_xor_sync(0xffffffffu, acc1, o);
        acc2 += __shfl_xor_sync(0xffffffffu, acc2, o);
      }
      if (lane == 0) {
        atomicAdd(&Arow[d1], acc1 + b2v);
        if (has2) atomicAdd(&Arow[d2], acc2 + b2v);
      }
    }
    __syncthreads();

    {
      const float4* Az = (const float4*)Arow;
      int n4 = cfg.Nc >> 2;
      for (int j4 = t; j4 < n4; j4 += 256) {
        float4 a = Az[j4];
        if (a.x > 0.f || a.y > 0.f || a.z > 0.f || a.w > 0.f) {
          float av[4] = {a.x, a.y, a.z, a.w};
#pragma unroll
          for (int c = 0; c < 4; c++) {
            if (av[c] > 0.f) {
              int j = j4 * 4 + c;
              unsigned m = (unsigned)i * (unsigned)cfg.Nc + (unsigned)j;
              unsigned bits = jax_bits(cfg.k0, cfg.k1, m);
              float f = __uint_as_float((bits >> 9) | 0x3f800000u) - 1.0f;
              float u = fmaxf(1e-10f, f + 1e-10f);
              float y = av[c] + (-logf(-logf(u)));
              int pos = atomicAdd(&ncand, 1);
              if (pos < CANDMAX) cand[pos] = packkey(y, j);
            }
          }
        }
      }
    }
    __syncthreads();
    int nc = ncand < CANDMAX ? ncand : CANDMAX;

    if (warp == 0) {
      unsigned long long prev = 0;
      for (int r = 0; r < 5; r++) {
        unsigned long long best = 0ull;
        for (int q = lane; q < nc; q += 32) {
          unsigned long long k = cand[q];
          if (k == prev) { cand[q] = 0ull; k = 0ull; }
          if (k > best) best = k;
        }
#pragma unroll
        for (int o = 16; o; o >>= 1) {
          unsigned long long v = __shfl_xor_sync(0xffffffffu, best, o);
          if (v > best) best = v;
        }
        if (lane == 0)
          sel5[r] = (best != 0ull)
                        ? (int)(0xFFFFFFFFu - (unsigned)(best & 0xFFFFFFFFull))
                        : -1;
        prev = best;
      }
      if (lane == 0) {
        int r = 0;
        while (r < 5 && sel5[r] >= 0) r++;
        for (int j = 0; j < cfg.Nc && r < 5; j++)
          if (!(Arow[j] > 0.f)) sel5[r++] = j;
        for (int q = 0; q < 5; q++) cfg.sel[i * 5 + q] = sel5[q];
      }
    }
    __syncthreads();

    int s0 = sel5[0], s1 = sel5[1], s2 = sel5[2], s3 = sel5[3], s4 = sel5[4];
    for (int e = t; e < nE; e += 256) {
      int p = cfg.rlst[b + e];
      int d = p & 4095;
      int eid = p >> 12;
      cfg.outW[eid] = (d == s0 || d == s1 || d == s2 || d == s3 || d == s4) ? 1.f : 0.f;
    }
  }
}

// ---------------- phase: node_out (block 0) ----------------
__device__ void do_node_out(const Mega& M, float* smf) {
  float* selfv = smf;
  float* mpp = smf + 128;
  float* mapv = smf + 256;
  float* agg = smf + 384;
  int t = threadIdx.x;
  int idx = M.idxPtr[0];
  if (t < 128) {
    selfv[t] = M.HP0a[(size_t)idx * HD + t];
    int b = idx * M.ppcap, nE = M.ppcnt[idx];
    float s = 0.f;
    for (int q = b; q < b + nE; q++) {
      int p = M.pplst[q];
      if (M.wpp[p >> 12] != 0.f) s += M.HP0a[(size_t)(p & 4095) * HD + t];
    }
    mpp[t] = s / fmaxf((float)nE, 1.f);
    b = idx * M.apcap; nE = M.apcnt[idx];
    s = 0.f;
    for (int q = b; q < b + nE; q++)
      s += M.HA0a[(size_t)(M.aplst[q] & 4095) * HD + t];
    mapv[t] = s / fmaxf((float)nE, 1.f);
  }
  __syncthreads();
  if (t < 128) {
    float a = 0.f;
    for (int k = 0; k < HD; k++)
      a += selfv[k] * M.Wselfp1[k * HD + t] + mpp[k] * M.Wpp1a[k * HD + t] +
           mapv[k] * M.Wap1a[k * HD + t];
    agg[t] = fmaxf(a, 0.f);
  }
  __syncthreads();
  if (t < 5) {
    float y = M.bc[t];
    for (int k = 0; k < HD; k++) y += agg[k] * M.Wc[k * 5 + t];
    M.yout[t] = y;
  }
}

// ---------------- the megakernel ----------------
__global__ __launch_bounds__(256, 5) void mega_kernel(Mega M) {
  extern __shared__ float smf[];
  int t = threadIdx.x;
  // P1: single-pass bucket fill (x8); CNT pre-zeroed by tail of prior launch
  {
    int tot8 = M.eStart[6] >> 3;
    for (int g = blockIdx.x * 256 + t; g < tot8; g += gridDim.x * 256) {
      int g8 = g * 8;
      int r = 0;
      while (g8 >= M.eStart[r + 1]) r++;
      int e = g8 - M.eStart[r];
      int4 ka = *(const int4*)(M.key[r] + e);
      int4 kb = *(const int4*)(M.key[r] + e + 4);
      int4 pa = *(const int4*)(M.part[r] + e);
      int4 pb = *(const int4*)(M.part[r] + e + 4);
      int pk = M.pack[r];
      int cap = M.cap[r];
      int* cnt = M.cnt[r];
      int* out = M.lst[r];
#define DOF(K, P, EE) { int pos = atomicAdd(&cnt[K], 1); \
      out[(K) * cap + pos] = (P) | (pk ? ((EE) << 12) : 0); }
      DOF(ka.x, pa.x, e)     DOF(ka.y, pa.y, e + 1)
      DOF(ka.z, pa.z, e + 2) DOF(ka.w, pa.w, e + 3)
      DOF(kb.x, pb.x, e + 4) DOF(kb.y, pb.y, e + 5)
      DOF(kb.z, pb.z, e + 6) DOF(kb.w, pb.w, e + 7)
#undef DOF
    }
  }
  gbar();
  do_gather(M.g1, 2, 0, gridDim.x);
  gbar();
  {
    int split = (gridDim.x > 384) ? 192 : (gridDim.x >> 1);
    if (blockIdx.x < split) do_gemm(M.gm1, smf, 0, split);
    else                    do_gather(M.g1 + 2, 2, split, gridDim.x - split);
  }
  gbar();
  do_gather(M.g2, 2, 0, gridDim.x);  gbar();
  do_gemm(M.gm2, smf, 0, gridDim.x); gbar();
  do_gemm(M.gmEP, smf, 0, gridDim.x); gbar();
  do_prune(M, smf);                  gbar();
  do_gather(M.g3, 2, 0, gridDim.x);  gbar();
  do_gemm(M.gm3, smf, 0, gridDim.x); gbar();
  if (blockIdx.x == 0) {
    do_node_out(M, smf);
    __syncthreads();
    for (int i = t; i < 4096; i += 256) { M.cnt[0][i] = 0; M.cnt[5][i] = 0; }
  } else {
    for (int i = (blockIdx.x - 1) * 256 + t; i < 4 * 4096;
         i += (gridDim.x - 1) * 256)
      M.cnt[1 + (i >> 12)][i & 4095] = 0;
  }
}

// ---------------- host launcher ----------------
extern "C" void kernel_launch(void* const* d_in, const int* in_sizes, int n_in,
                              void* d_out, int out_size) {
  const float* x_p = (const float*)d_in[0];
  const float* x_a = (const float*)d_in[1];
  const int* ei_pp = (const int*)d_in[2];
  const int* ei_aa = (const int*)d_in[3];
  const int* ei_pa = (const int*)d_in[4];
  const int* ei_ap = (const int*)d_in[5];
  const int* idxPtr = (const int*)d_in[8];
  const float* Ws_p0 = (const float*)d_in[9];
  const float* Ws_p1 = (const float*)d_in[10];
  const float* Ws_a0 = (const float*)d_in[11];
  const float* Ws_a1 = (const float*)d_in[12];
  const float* Wpp0 = (const float*)d_in[13];
  const float* Wpp1 = (const float*)d_in[14];
  const float* Waa0 = (const float*)d_in[15];
  const float* Waa1 = (const float*)d_in[16];
  const float* Wpa0 = (const float*)d_in[17];
  const float* Wap0 = (const float*)d_in[19];
  const float* Wap1 = (const float*)d_in[20];
  const float* Wep1_pp = (const float*)d_in[21];
  const float* bep1_pp = (const float*)d_in[22];
  const float* Wep2_pp = (const float*)d_in[23];
  const float* bep2_pp = (const float*)d_in[24];
  const float* Wep1_aa = (const float*)d_in[25];
  const float* bep1_aa = (const float*)d_in[26];
  const float* Wep2_aa = (const float*)d_in[27];
  const float* bep2_aa = (const float*)d_in[28];
  const float* Wc = (const float*)d_in[29];
  const float* bc = (const float*)d_in[30];

  int Epp = in_sizes[2] / 2, Eaa = in_sizes[3] / 2;
  int Epa = in_sizes[4] / 2, Eap = in_sizes[5] / 2;
  const int* pp_src = ei_pp;  const int* pp_dst = ei_pp + Epp;
  const int* aa_src = ei_aa;  const int* aa_dst = ei_aa + Eaa;
  const int* pa_src = ei_pa;  const int* pa_dst = ei_pa + Epa;
  const int* ap_src = ei_ap;  const int* ap_dst = ei_ap + Eap;

  unsigned kpp0, kpp1, kaa0, kaa1;
  tf2x32(0u, 42u, 0u, 0u, kpp0, kpp1);
  tf2x32(0u, 42u, 0u, 1u, kaa0, kaa1);

  void* basep = nullptr;
  cudaGetSymbolAddress(&basep, g_arena);
  unsigned char* ar = (unsigned char*)basep;
  size_t off = 0;
  auto carve = [&](size_t bytes) -> unsigned char* {
    unsigned char* p = ar + off;
    off += (bytes + 255) & ~(size_t)255;
    return p;
  };
  float* AGGP  = (float*)carve((size_t)NPAP * HD * 4);
  float* AGGA  = (float*)carve((size_t)NAUT * HD * 4);
  float* AGGP2 = (float*)carve((size_t)NPAP * HD * 4);
  float* AGGA2 = (float*)carve((size_t)NAUT * HD * 4);
  float* HP0 = (float*)carve((size_t)NPAP * HD * 4);
  float* HP1 = (float*)carve((size_t)NPAP * HD * 4);
  float* HA0 = (float*)carve((size_t)NAUT * HD * 4);
  float* HA1 = (float*)carve((size_t)NAUT * HD * 4);
  float* UP = (float*)carve((size_t)NPAP * 256 * 4);
  float* VP = (float*)carve((size_t)NPAP * 256 * 4);
  float* UA = (float*)carve((size_t)NAUT * 256 * 4);
  float* VA = (float*)carve((size_t)NAUT * 256 * 4);
  int* CNT = (int*)carve(6 * 4096 * 4);
  int* P0 = (int*)carve((size_t)NPAP * 128 * 4);
  int* P1 = (int*)carve((size_t)NPAP * 128 * 4);
  int* P2 = (int*)carve((size_t)NAUT * 128 * 4);
  int* P3 = (int*)carve((size_t)NAUT * 128 * 4);
  int* P4 = (int*)carve((size_t)NAUT * 256 * 4);
  int* P5 = (int*)carve((size_t)NPAP * 128 * 4);
  int* SELPP = (int*)carve((size_t)NPAP * 5 * 4);
  int* SELAA = (int*)carve((size_t)NAUT * 5 * 4);

  float* out_f = (float*)d_out;
  float* WPPo = out_f + 5;
  float* WAAo = out_f + 5 + Epp;

  Mega M;
  const int* keys[6]  = {pp_dst, pp_src, aa_dst, aa_src, pa_dst, ap_dst};
  const int* parts[6] = {pp_src, pp_dst, aa_src, aa_dst, pa_src, ap_src};
  int Es[6] = {Epp, Epp, Eaa, Eaa, Epa, Eap};
  int packs[6] = {1, 1, 1, 1, 0, 0};
  int caps[6] = {128, 128, 128, 128, 256, 128};
  int* lsts[6] = {P0, P1, P2, P3, P4, P5};
  int run = 0;
  for (int r = 0; r < 6; r++) {
    M.key[r] = keys[r]; M.part[r] = parts[r];
    M.cnt[r] = CNT + r * 4096; M.lst[r] = lsts[r];
    M.pack[r] = packs[r]; M.cap[r] = caps[r];
    M.eStart[r] = run; run += Es[r];
  }
  M.eStart[6] = run;

  M.g1[0] = {CNT + 0 * 4096, P0, 128, x_p, AGGP, nullptr, NPAP};
  M.g1[1] = {CNT + 2 * 4096, P2, 128, x_a, AGGA, nullptr, NAUT};
  M.g1[2] = {CNT + 5 * 4096, P5, 128, x_a, AGGP2, nullptr, NPAP};
  M.g1[3] = {CNT + 4 * 4096, P4, 256, x_p, AGGA2, nullptr, NAUT};
  M.g2[0] = {CNT + 0 * 4096, P0, 128, HP0, AGGP, nullptr, NPAP};
  M.g2[1] = {CNT + 2 * 4096, P2, 128, HA0, AGGA, nullptr, NAUT};
  M.g3[0] = {CNT + 0 * 4096, P0, 128, x_p, AGGP, WPPo, NPAP};
  M.g3[1] = {CNT + 2 * 4096, P2, 128, x_a, AGGA, WAAo, NAUT};

  M.gm1.njobs = 2; M.gm1.ntiles = 192;
  M.gm1.j[0] = {{x_p, AGGP, nullptr}, {Ws_p0, Wpp0, nullptr}, HP0, 128, 2, 1, 0};
  M.gm1.j[1] = {{x_a, AGGA, nullptr}, {Ws_a0, Waa0, nullptr}, HA0, 128, 2, 1, 128};
  M.gm2.njobs = 2; M.gm2.ntiles = 192;
  M.gm2.j[0] = {{HP0, AGGP, nullptr}, {Ws_p1, Wpp1, nullptr}, HP1, 128, 2, 1, 0};
  M.gm2.j[1] = {{HA0, AGGA, nullptr}, {Ws_a1, Waa1, nullptr}, HA1, 128, 2, 1, 128};
  M.gmEP.njobs = 4; M.gmEP.ntiles = 768;
  M.gmEP.j[0] = {{HP1, nullptr, nullptr}, {Wep1_pp, nullptr, nullptr}, UP, 256, 1, 0, 0};
  M.gmEP.j[1] = {{HP1, nullptr, nullptr}, {Wep1_pp + 128 * 256, nullptr, nullptr}, VP, 256, 1, 0, 256};
  M.gmEP.j[2] = {{HA1, nullptr, nullptr}, {Wep1_aa, nullptr, nullptr}, UA, 256, 1, 0, 512};
  M.gmEP.j[3] = {{HA1, nullptr, nullptr}, {Wep1_aa + 128 * 256, nullptr, nullptr}, VA, 256, 1, 0, 640};
  M.gm3.njobs = 2; M.gm3.ntiles = 192;
  M.gm3.j[0] = {{x_p, AGGP, AGGP2}, {Ws_p0, Wpp0, Wap0}, HP0, 128, 3, 1, 0};
  M.gm3.j[1] = {{x_a, AGGA, AGGA2}, {Ws_a0, Waa0, Wpa0}, HA0, 128, 3, 1, 128};

  M.cp = {CNT + 1 * 4096, P1, 128, UP, VP, bep1_pp, Wep2_pp, bep2_pp,
          4096, kpp0, kpp1, SELPP, WPPo};
  M.ca = {CNT + 3 * 4096, P3, 128, UA, VA, bep1_aa, Wep2_aa, bep2_aa,
          2048, kaa0, kaa1, SELAA, WAAo};
  M.nPP = NPAP; M.nRows = NPAP + NAUT;

  M.idxPtr = idxPtr; M.HP0a = HP0; M.HA0a = HA0;
  M.ppcnt = CNT + 0 * 4096; M.pplst = P0; M.ppcap = 128; M.wpp = WPPo;
  M.apcnt = CNT + 5 * 4096; M.aplst = P5; M.apcap = 128;
  M.Wselfp1 = Ws_p1; M.Wpp1a = Wpp1; M.Wap1a = Wap1;
  M.Wc = Wc; M.bc = bc; M.yout = out_f;

  int nsm = 148;
  cudaDeviceGetAttribute(&nsm, cudaDevAttrMultiProcessorCount, 0);
  int occ = 0;
  cudaOccupancyMaxActiveBlocksPerMultiprocessor(&occ, mega_kernel, 256, SMEMB);
  if (occ < 1) occ = 1;
  long long grid = (long long)occ * nsm;
  if (grid > 1024) grid = 1024;
  mega_kernel<<<(int)grid, 256, SMEMB>>>(M);
}